// round 13
// baseline (speedup 1.0000x reference)
#include <cuda_runtime.h>
#include <math.h>
#include <stdint.h>

// Problem constants
#define BB 4
#define NN 1024
#define DD 1024
#define HH 16
#define HDIM 64
#define MROWS (BB * NN)          // 4096

// Scratch (device globals; no allocations allowed)
__device__ float g_q[BB * HH * NN * HDIM];   // [B,H,N,HD]
__device__ float g_k[BB * HH * NN * HDIM];
__device__ float g_v[BB * HH * NN * HDIM];
__device__ float g_ctx[BB * NN * DD];        // [B,N,H,HD]
__device__ float g_msg[MROWS * DD];          // out-proj result (message)
__device__ float g_h[MROWS * 2 * DD];        // FFN hidden, rows of 2048

__device__ __forceinline__ void mma_tf32(float* c, const uint32_t* a, const uint32_t* b) {
    asm volatile(
        "mma.sync.aligned.m16n8k8.row.col.f32.tf32.tf32.f32 "
        "{%0,%1,%2,%3}, {%4,%5,%6,%7}, {%8,%9}, {%0,%1,%2,%3};"
        : "+f"(c[0]), "+f"(c[1]), "+f"(c[2]), "+f"(c[3])
        : "r"(a[0]), "r"(a[1]), "r"(a[2]), "r"(a[3]), "r"(b[0]), "r"(b[1]));
}

// ldmatrix x4: four 8-row x 16-byte tiles; as tf32, lane l gets (row l/4, col l%4)
__device__ __forceinline__ void ldsm4(uint32_t* r, uint32_t addr) {
    asm volatile(
        "ldmatrix.sync.aligned.m8n8.x4.shared.b16 {%0,%1,%2,%3}, [%4];"
        : "=r"(r[0]), "=r"(r[1]), "=r"(r[2]), "=r"(r[3]) : "r"(addr));
}

__device__ __forceinline__ uint32_t smem_u32(const void* p) {
    return (uint32_t)__cvta_generic_to_shared(p);
}
#define CP_ASYNC16(dst, src) \
    asm volatile("cp.async.cg.shared.global [%0], [%1], 16;" :: "r"(dst), "l"(src))
#define CP_COMMIT() asm volatile("cp.async.commit_group;" ::: "memory")
#define CP_WAIT1()  asm volatile("cp.async.wait_group 1;" ::: "memory")
#define CP_WAIT2()  asm volatile("cp.async.wait_group 2;" ::: "memory")

// ---------------------------------------------------------------------------
// TF32 tensor-core GEMM:  C[M,Ncol] = A[M,K] @ W[Ncol,K]^T + bias
// 128x128 block tile, 8 warps of 32x64, 256 threads (regs forced <=128 so
// 2 CTAs/SM = 16 warps/SM), 4-stage cp.async, ONE barrier per K-tile,
// fragments via ldmatrix.x4.
// mode 0: A=concat(x, g_msg) -> g_h            (FFN1, virtual concat)
// mode 1: A=Ain(x) -> scatter to g_q/g_k/g_v   (QKV)
// mode 2: A=g_ctx  -> g_msg                    (out-proj)
// mode 3: A=g_h    -> Cout = resid + result    (FFN2 + residual)
// ---------------------------------------------------------------------------
#define BM 128
#define BN 128
#define BK 16
#define APITCH 20   // 80B rows: 16B-aligned chunks; LDSM wavefronts conflict-free
#define STAGES 4
#define GEMM_SMEM (STAGES * (BM + BN) * APITCH * 4)   // 81920 B

__global__ __launch_bounds__(256, 2) void gemm_kernel(
    const float* __restrict__ Ain, const float* __restrict__ W,
    const float* __restrict__ bias, float* __restrict__ Cout,
    const float* __restrict__ resid, int M, int Ncol, int K, int mode)
{
    extern __shared__ float dyn[];
    float (*As)[BM][APITCH] = (float(*)[BM][APITCH])dyn;
    float (*Ws)[BN][APITCH] = (float(*)[BN][APITCH])(dyn + STAGES * BM * APITCH);

    const float* A = (mode == 2) ? g_ctx : (mode == 3) ? g_h : Ain;

    int tid = threadIdx.x;
    int lane = tid & 31;
    int wid = tid >> 5;        // 0..7
    int g = lane >> 2, t = lane & 3;
    int wm = wid & 3;          // 4 x 32 rows
    int wn = wid >> 2;         // 2 x 64 cols
    int m0 = blockIdx.y * BM, n0 = blockIdx.x * BN;

    float acc[2][8][4];
#pragma unroll
    for (int i = 0; i < 2; ++i)
#pragma unroll
        for (int j = 0; j < 8; ++j)
#pragma unroll
            for (int r = 0; r < 4; ++r) acc[i][j][r] = 0.f;

    int nt = K / BK;
    int lrow = tid >> 2, lkq = (tid & 3) * 4;   // this thread's load slot

    auto issue = [&](int s, int k0) {
        const float* abase;
        if (mode == 0)   // virtual concat([x, g_msg]) along K
            abase = (k0 < 1024) ? (Ain + k0) : (g_msg + (k0 - 1024));
        else
            abase = A + k0;
        int ak = (mode == 0) ? 1024 : K;
#pragma unroll
        for (int h = 0; h < 2; ++h) {
            int row = lrow + h * 64;
            CP_ASYNC16(smem_u32(&As[s][row][lkq]),
                       abase + (size_t)(m0 + row) * ak + lkq);
            CP_ASYNC16(smem_u32(&Ws[s][row][lkq]),
                       W + (size_t)(n0 + row) * K + k0 + lkq);
        }
        CP_COMMIT();
    };

    // ldmatrix lane-address offsets (bytes, within one stage)
    uint32_t as_base = smem_u32(dyn);
    uint32_t ws_base = smem_u32(dyn + STAGES * BM * APITCH);
    int grp01 = (lane >> 3) & 1;   // matrix-pair selector within x4
    int grp23 = lane >> 4;
    // A: m0..m3 = (rows 0-7,k0-3),(rows 8-15,k0-3),(rows 0-7,k4-7),(rows 8-15,k4-7)
    uint32_t aoff = (uint32_t)(((wm * 32 + (lane & 7) + 8 * grp01) * APITCH
                                + 4 * grp23) * 4);
    // B: m0..m3 = (tn even,f0),(tn even,f1),(tn odd,f0),(tn odd,f1)
    uint32_t boff = (uint32_t)(((wn * 64 + grp23 * 8 + (lane & 7)) * APITCH
                                + 4 * grp01) * 4);

    issue(0, 0);
    issue(1, BK);
    issue(2, 2 * BK);

    for (int tt = 0; tt < nt; ++tt) {
        int buf = tt % STAGES;
        CP_WAIT2();
        __syncthreads();

        int nk = tt + 3;
        if (nk < nt) issue(nk % STAGES, nk * BK);
        else CP_COMMIT();   // empty group keeps wait_group arithmetic exact

        uint32_t as_s = as_base + (uint32_t)(buf * BM * APITCH * 4) + aoff;
        uint32_t ws_s = ws_base + (uint32_t)(buf * BN * APITCH * 4) + boff;

#pragma unroll
        for (int kk = 0; kk < BK; kk += 8) {
            uint32_t af[2][4], bf4[4][4];
#pragma unroll
            for (int tm = 0; tm < 2; ++tm)
                ldsm4(af[tm], as_s + kk * 4 + tm * (16 * APITCH * 4));
#pragma unroll
            for (int tnp = 0; tnp < 4; ++tnp)
                ldsm4(bf4[tnp], ws_s + kk * 4 + tnp * (16 * APITCH * 4));
#pragma unroll
            for (int tm = 0; tm < 2; ++tm)
#pragma unroll
                for (int tn = 0; tn < 8; ++tn)
                    mma_tf32(acc[tm][tn], af[tm], &bf4[tn >> 1][(tn & 1) << 1]);
        }
    }

    // epilogue: c0:(r, 2t) c1:(r, 2t+1) c2:(r+8, 2t) c3:(r+8, 2t+1)
    int rbase = m0 + wm * 32 + g;
    int cbase = n0 + wn * 64 + 2 * t;
#pragma unroll
    for (int tm = 0; tm < 2; ++tm) {
#pragma unroll
        for (int tn = 0; tn < 8; ++tn) {
#pragma unroll
            for (int r = 0; r < 4; ++r) {
                int m = rbase + tm * 16 + ((r >> 1) ? 8 : 0);
                int col = cbase + tn * 8 + (r & 1);
                float v = acc[tm][tn][r] + bias[col];
                int b = m >> 10, n = m & 1023;
                if (mode == 0) {
                    g_h[(size_t)m * Ncol + col] = v;
                } else if (mode == 2) {
                    g_msg[(size_t)m * 1024 + col] = v;
                } else if (mode == 3) {
                    Cout[(size_t)m * Ncol + col] = v + resid[(size_t)m * Ncol + col];
                } else { // mode 1: QKV scatter
                    int h = col / 192;
                    int rem = col - h * 192;
                    int d = rem / 3;
                    int s = rem - d * 3;
                    size_t di = (((size_t)(b * HH + h)) * NN + n) * HDIM + d;
                    if (s == 0) g_q[di] = v;
                    else if (s == 1) g_k[di] = v;
                    else g_v[di] = v;
                }
            }
        }
    }
}

// ---------------------------------------------------------------------------
// RoPE in-place on g_q and g_k.  encoding: [2, B, 1, N, HD]
// ---------------------------------------------------------------------------
__global__ void rope_kernel(const float* __restrict__ enc)
{
    const int PH = BB * HH * NN * HDIM / 2;
    int p = blockIdx.x * blockDim.x + threadIdx.x;
    if (p >= 2 * PH) return;
    float* t = (p < PH) ? g_q : g_k;
    int pp = (p < PH) ? p : p - PH;
    int e = pp * 2;
    int d = e & 63;
    int n = (e >> 6) & 1023;
    int bh = e >> 16;
    int b = bh >> 4;
    float t0 = t[e], t1 = t[e + 1];
    size_t eb = ((size_t)(b * NN + n)) * HDIM + d;
    const int SINOFF = BB * NN * HDIM;
    float c0 = enc[eb], c1 = enc[eb + 1];
    float s0 = enc[eb + SINOFF], s1 = enc[eb + SINOFF + 1];
    t[e]     = t0 * c0 - t1 * s0;
    t[e + 1] = t1 * c1 + t0 * s1;
}

// ---------------------------------------------------------------------------
// Flash attention on tensor cores (tf32 m16n8k8, raw fp32 operands).
// 128 query rows (8 warps x 16), key tiles of 64, fixed-max softmax.
// 3-stage cp.async ring for K/V; K fragments via ldmatrix.x4.
// ---------------------------------------------------------------------------
#define KP 68
#define VP 72
#define ATT_STAGES 3
#define ATT_SMEM (ATT_STAGES * 64 * (KP + VP) * 4)

__global__ __launch_bounds__(256, 2) void attn_kernel()
{
    extern __shared__ float adyn[];
    float (*Ks)[64][KP] = (float(*)[64][KP])adyn;
    float (*Vs)[64][VP] = (float(*)[64][VP])(adyn + ATT_STAGES * 64 * KP);

    int bh = blockIdx.y;
    int qt = blockIdx.x;
    int tid = threadIdx.x;
    int lane = tid & 31;
    int wid = tid >> 5;
    int g = lane >> 2, t = lane & 3;

    const float* qbase = g_q + (size_t)bh * NN * HDIM + (size_t)qt * 128 * HDIM;
    const float* kbase = g_k + (size_t)bh * NN * HDIM;
    const float* vbase = g_v + (size_t)bh * NN * HDIM;

    auto issueKV = [&](int s, int kt2) {
        const float* kb = kbase + (size_t)kt2 * 64 * HDIM;
        const float* vb = vbase + (size_t)kt2 * 64 * HDIM;
#pragma unroll
        for (int h2 = 0; h2 < 4; ++h2) {
            int f = tid + h2 * 256;
            int r = f >> 4, cq = (f & 15) * 4;
            CP_ASYNC16(smem_u32(&Ks[s][r][cq]), kb + (size_t)r * HDIM + cq);
            CP_ASYNC16(smem_u32(&Vs[s][r][cq]), vb + (size_t)r * HDIM + cq);
        }
        CP_COMMIT();
    };

    uint32_t qf[8][4];
    {
        const float* q0 = qbase + (size_t)(wid * 16 + g) * HDIM;
        const float* q1 = q0 + 8 * HDIM;
#pragma unroll
        for (int kc = 0; kc < 8; ++kc) {
            int k0 = kc * 8 + t;
            qf[kc][0] = __float_as_uint(q0[k0] * 0.125f);
            qf[kc][1] = __float_as_uint(q1[k0] * 0.125f);
            qf[kc][2] = __float_as_uint(q0[k0 + 4] * 0.125f);
            qf[kc][3] = __float_as_uint(q1[k0 + 4] * 0.125f);
        }
    }

    float l0 = 0.f, l1 = 0.f;
    float O[8][4];
#pragma unroll
    for (int i = 0; i < 8; ++i)
#pragma unroll
        for (int r = 0; r < 4; ++r) O[i][r] = 0.f;

    const int sl0 = (lane & ~3) | (t >> 1);
    const int sl1 = sl0 + 2;

    uint32_t ks_base = smem_u32(adyn);
    int grp01 = (lane >> 3) & 1;
    int grp23 = lane >> 4;
    uint32_t koff = (uint32_t)(((grp23 * 8 + (lane & 7)) * KP + 4 * grp01) * 4);

    issueKV(0, 0);
    issueKV(1, 1);

    for (int kt = 0; kt < 16; ++kt) {
        int buf = kt % ATT_STAGES;
        CP_WAIT1();
        __syncthreads();

        int nk = kt + 2;
        if (nk < 16) issueKV(nk % ATT_STAGES, nk);
        else CP_COMMIT();

        float S[8][4];
#pragma unroll
        for (int i = 0; i < 8; ++i)
#pragma unroll
            for (int r = 0; r < 4; ++r) S[i][r] = 0.f;

        uint32_t ks_s = ks_base + (uint32_t)(buf * 64 * KP * 4) + koff;
#pragma unroll
        for (int kc = 0; kc < 8; ++kc) {
#pragma unroll
            for (int knp = 0; knp < 4; ++knp) {
                uint32_t kf[4];
                ldsm4(kf, ks_s + kc * 32 + knp * (16 * KP * 4));
                mma_tf32(S[2 * knp],     qf[kc], &kf[0]);
                mma_tf32(S[2 * knp + 1], qf[kc], &kf[2]);
            }
        }

#pragma unroll
        for (int i = 0; i < 8; ++i) {
            float p0 = __expf(S[i][0]);
            float p1 = __expf(S[i][1]);
            float p2 = __expf(S[i][2]);
            float p3 = __expf(S[i][3]);
            l0 += p0 + p1; l1 += p2 + p3;
            S[i][0] = p0; S[i][1] = p1; S[i][2] = p2; S[i][3] = p3;
        }

#pragma unroll
        for (int kc = 0; kc < 8; ++kc) {
            float v00 = __shfl_sync(0xffffffffu, S[kc][0], sl0);
            float v01 = __shfl_sync(0xffffffffu, S[kc][1], sl0);
            float v10 = __shfl_sync(0xffffffffu, S[kc][2], sl0);
            float v11 = __shfl_sync(0xffffffffu, S[kc][3], sl0);
            float v20 = __shfl_sync(0xffffffffu, S[kc][0], sl1);
            float v21 = __shfl_sync(0xffffffffu, S[kc][1], sl1);
            float v30 = __shfl_sync(0xffffffffu, S[kc][2], sl1);
            float v31 = __shfl_sync(0xffffffffu, S[kc][3], sl1);
            uint32_t af[4];
            af[0] = __float_as_uint((t & 1) ? v01 : v00);
            af[1] = __float_as_uint((t & 1) ? v11 : v10);
            af[2] = __float_as_uint((t & 1) ? v21 : v20);
            af[3] = __float_as_uint((t & 1) ? v31 : v30);
#pragma unroll
            for (int ntile = 0; ntile < 8; ++ntile) {
                uint32_t bf[2];
                bf[0] = __float_as_uint(Vs[buf][kc * 8 + t][ntile * 8 + g]);
                bf[1] = __float_as_uint(Vs[buf][kc * 8 + t + 4][ntile * 8 + g]);
                mma_tf32(O[ntile], af, bf);
            }
        }
    }

    l0 += __shfl_xor_sync(0xffffffffu, l0, 1);
    l0 += __shfl_xor_sync(0xffffffffu, l0, 2);
    l1 += __shfl_xor_sync(0xffffffffu, l1, 1);
    l1 += __shfl_xor_sync(0xffffffffu, l1, 2);

    float i0 = 1.f / l0, i1 = 1.f / l1;
    int b = bh >> 4, h = bh & 15;
    int r0 = qt * 128 + wid * 16 + g;
    float* d0 = g_ctx + (((size_t)(b * NN + r0)) * HH + h) * HDIM;
    float* d1 = g_ctx + (((size_t)(b * NN + r0 + 8)) * HH + h) * HDIM;
#pragma unroll
    for (int ntile = 0; ntile < 8; ++ntile) {
        int c = ntile * 8 + 2 * t;
        d0[c]     = O[ntile][0] * i0;
        d0[c + 1] = O[ntile][1] * i0;
        d1[c]     = O[ntile][2] * i1;
        d1[c + 1] = O[ntile][3] * i1;
    }
}

// ---------------------------------------------------------------------------
// LayerNorm(2048) + exact GELU, in-place on g_h.
// ---------------------------------------------------------------------------
__global__ __launch_bounds__(256) void ln_gelu_kernel(
    const float* __restrict__ lng, const float* __restrict__ lnb)
{
    int row = blockIdx.x;
    float* hr = g_h + (size_t)row * 2048;
    int tid = threadIdx.x;
    float v[8];
    float s = 0.f, s2 = 0.f;
#pragma unroll
    for (int i = 0; i < 8; ++i) {
        float t = hr[tid + i * 256];
        v[i] = t; s += t; s2 += t * t;
    }
#pragma unroll
    for (int o = 16; o; o >>= 1) {
        s  += __shfl_xor_sync(0xffffffffu, s,  o);
        s2 += __shfl_xor_sync(0xffffffffu, s2, o);
    }
    __shared__ float rs[8], rs2[8];
    __shared__ float sm, si;
    int wid = tid >> 5, lane = tid & 31;
    if (!lane) { rs[wid] = s; rs2[wid] = s2; }
    __syncthreads();
    if (tid == 0) {
        float S = 0.f, S2 = 0.f;
#pragma unroll
        for (int i = 0; i < 8; ++i) { S += rs[i]; S2 += rs2[i]; }
        float mean = S * (1.f / 2048.f);
        float var = S2 * (1.f / 2048.f) - mean * mean;
        sm = mean;
        si = rsqrtf(var + 1e-5f);
    }
    __syncthreads();
    float mean = sm, inv = si;
#pragma unroll
    for (int i = 0; i < 8; ++i) {
        int col = tid + i * 256;
        float t = (v[i] - mean) * inv * lng[col] + lnb[col];
        t = 0.5f * t * (1.f + erff(t * 0.70710678118654752f));
        hr[col] = t;
    }
}

// ---------------------------------------------------------------------------
extern "C" void kernel_launch(void* const* d_in, const int* in_sizes, int n_in,
                              void* d_out, int out_size)
{
    const float* x       = (const float*)d_in[0];
    const float* enc     = (const float*)d_in[1];
    const float* Wqkv_w  = (const float*)d_in[2];
    const float* Wqkv_b  = (const float*)d_in[3];
    const float* out_w   = (const float*)d_in[4];
    const float* out_b   = (const float*)d_in[5];
    const float* ffn1_w  = (const float*)d_in[6];
    const float* ffn1_b  = (const float*)d_in[7];
    const float* ln_g    = (const float*)d_in[8];
    const float* ln_b    = (const float*)d_in[9];
    const float* ffn2_w  = (const float*)d_in[10];
    const float* ffn2_b  = (const float*)d_in[11];
    float* out = (float*)d_out;

    cudaFuncSetAttribute(gemm_kernel,
                         cudaFuncAttributeMaxDynamicSharedMemorySize, GEMM_SMEM);
    cudaFuncSetAttribute(attn_kernel,
                         cudaFuncAttributeMaxDynamicSharedMemorySize, ATT_SMEM);

    // 1) QKV projection + scatter to q/k/v   (M=4096, N=3072, K=1024)
    gemm_kernel<<<dim3(3072 / BN, MROWS / BM), 256, GEMM_SMEM>>>(
        x, Wqkv_w, Wqkv_b, nullptr, nullptr, MROWS, 3072, 1024, 1);

    // 2) RoPE on q and k
    rope_kernel<<<(2 * BB * HH * NN * HDIM / 2 + 255) / 256, 256>>>(enc);

    // 3) attention -> g_ctx [B,N,H,HD]
    attn_kernel<<<dim3(NN / 128, BB * HH), 256, ATT_SMEM>>>();

    // 4) out projection -> g_msg   (M=4096, N=1024, K=1024)
    gemm_kernel<<<dim3(1024 / BN, MROWS / BM), 256, GEMM_SMEM>>>(
        nullptr, out_w, out_b, nullptr, nullptr, MROWS, 1024, 1024, 2);

    // 5) FFN1 (A = virtual concat of x and g_msg) -> g_h  (M=4096, N=2048, K=2048)
    gemm_kernel<<<dim3(2048 / BN, MROWS / BM), 256, GEMM_SMEM>>>(
        x, ffn1_w, ffn1_b, nullptr, nullptr, MROWS, 2048, 2048, 0);

    // 6) LayerNorm + GELU in-place
    ln_gelu_kernel<<<MROWS, 256>>>(ln_g, ln_b);

    // 7) FFN2 + residual -> d_out   (M=4096, N=1024, K=2048)
    gemm_kernel<<<dim3(1024 / BN, MROWS / BM), 256, GEMM_SMEM>>>(
        x, ffn2_w, ffn2_b, out, x, MROWS, 1024, 2048, 3);
}

// round 14
// speedup vs baseline: 1.1242x; 1.1242x over previous
#include <cuda_runtime.h>
#include <math.h>
#include <stdint.h>

// Problem constants
#define BB 4
#define NN 1024
#define DD 1024
#define HH 16
#define HDIM 64
#define MROWS (BB * NN)          // 4096

// Scratch (device globals; no allocations allowed)
__device__ float g_q[BB * HH * NN * HDIM];   // [B,H,N,HD]
__device__ float g_k[BB * HH * NN * HDIM];
__device__ float g_v[BB * HH * NN * HDIM];
__device__ float g_ctx[BB * NN * DD];        // [B,N,H,HD]
__device__ float g_msg[MROWS * DD];          // out-proj result (message)
__device__ float g_h[MROWS * 2 * DD];        // FFN hidden, rows of 2048

__device__ __forceinline__ void mma_tf32(float* c, const uint32_t* a, const uint32_t* b) {
    asm volatile(
        "mma.sync.aligned.m16n8k8.row.col.f32.tf32.tf32.f32 "
        "{%0,%1,%2,%3}, {%4,%5,%6,%7}, {%8,%9}, {%0,%1,%2,%3};"
        : "+f"(c[0]), "+f"(c[1]), "+f"(c[2]), "+f"(c[3])
        : "r"(a[0]), "r"(a[1]), "r"(a[2]), "r"(a[3]), "r"(b[0]), "r"(b[1]));
}

// ldmatrix x4: four 8-row x 16-byte tiles; as tf32, lane l gets (row l/4, col l%4)
__device__ __forceinline__ void ldsm4(uint32_t* r, uint32_t addr) {
    asm volatile(
        "ldmatrix.sync.aligned.m8n8.x4.shared.b16 {%0,%1,%2,%3}, [%4];"
        : "=r"(r[0]), "=r"(r[1]), "=r"(r[2]), "=r"(r[3]) : "r"(addr));
}

__device__ __forceinline__ uint32_t smem_u32(const void* p) {
    return (uint32_t)__cvta_generic_to_shared(p);
}
#define CP_ASYNC16(dst, src) \
    asm volatile("cp.async.cg.shared.global [%0], [%1], 16;" :: "r"(dst), "l"(src))
#define CP_COMMIT() asm volatile("cp.async.commit_group;" ::: "memory")
#define CP_WAIT2()  asm volatile("cp.async.wait_group 2;" ::: "memory")
#define CP_WAIT1()  asm volatile("cp.async.wait_group 1;" ::: "memory")

// QKV column permutation: logical col' in [0,3072) = [q | k | v], d contiguous.
// orig W row = h*192 + d*3 + s  where s = col'>>10, h = (col'&1023)>>6, d = col'&63
__device__ __forceinline__ int qkv_perm(int colp) {
    int s = colp >> 10;
    int w = colp & 1023;
    int h = w >> 6;
    int d = w & 63;
    return h * 192 + d * 3 + s;
}

// ---------------------------------------------------------------------------
// TF32 tensor-core GEMM (R12 shape):  C[M,Ncol] = A[M,K] @ W[Ncol,K]^T + bias
// 128x128 block tile, 4 warps of 64x64, 128 threads, 4-stage cp.async,
// ONE barrier per K-tile; fragments via ldmatrix.x4. 2 CTAs/SM.
// mode 0: A=concat(x, g_msg) -> g_h            (FFN1, virtual concat)
// mode 1: A=Ain(x), W rows permuted -> packed q/k/v   (QKV)
// mode 2: A=g_ctx  -> g_msg                    (out-proj)
// mode 3: A=g_h    -> Cout = resid + result    (FFN2 + residual)
// ---------------------------------------------------------------------------
#define BM 128
#define BN 128
#define BK 16
#define APITCH 20   // 80B rows: 16B-aligned chunks; LDSM wavefronts conflict-free
#define STAGES 4
#define GEMM_SMEM (STAGES * (BM + BN) * APITCH * 4)   // 81920 B

__global__ __launch_bounds__(128) void gemm_kernel(
    const float* __restrict__ Ain, const float* __restrict__ W,
    const float* __restrict__ bias, float* __restrict__ Cout,
    const float* __restrict__ resid, int M, int Ncol, int K, int mode)
{
    extern __shared__ float dyn[];
    float (*As)[BM][APITCH] = (float(*)[BM][APITCH])dyn;
    float (*Ws)[BN][APITCH] = (float(*)[BN][APITCH])(dyn + STAGES * BM * APITCH);

    const float* A = (mode == 2) ? g_ctx : (mode == 3) ? g_h : Ain;

    int tid = threadIdx.x;
    int lane = tid & 31;
    int wid = tid >> 5;
    int g = lane >> 2, t = lane & 3;
    int wm = wid >> 1;
    int wn = wid & 1;
    int m0 = blockIdx.y * BM, n0 = blockIdx.x * BN;

    float acc[4][8][4];
#pragma unroll
    for (int i = 0; i < 4; ++i)
#pragma unroll
        for (int j = 0; j < 8; ++j)
#pragma unroll
            for (int r = 0; r < 4; ++r) acc[i][j][r] = 0.f;

    int nt = K / BK;
    int lrow = tid >> 2, lkq = (tid & 3) * 4;   // this thread's load slot

    // Pre-resolved W row indices (permuted for QKV), 4 rows per thread
    int wrow[4];
#pragma unroll
    for (int h = 0; h < 4; ++h) {
        int row = n0 + lrow + h * 32;
        wrow[h] = (mode == 1) ? qkv_perm(row) : row;
    }

    auto issue = [&](int s, int k0) {
        const float* abase;
        if (mode == 0)   // virtual concat([x, g_msg]) along K
            abase = (k0 < 1024) ? (Ain + k0) : (g_msg + (k0 - 1024));
        else
            abase = A + k0;
        int ak = (mode == 0) ? 1024 : K;
#pragma unroll
        for (int h = 0; h < 4; ++h) {
            int row = lrow + h * 32;
            CP_ASYNC16(smem_u32(&As[s][row][lkq]),
                       abase + (size_t)(m0 + row) * ak + lkq);
            CP_ASYNC16(smem_u32(&Ws[s][row][lkq]),
                       W + (size_t)wrow[h] * K + k0 + lkq);
        }
        CP_COMMIT();
    };

    // ldmatrix lane-address offsets (bytes, within one stage)
    uint32_t as_base = smem_u32(dyn);
    uint32_t ws_base = smem_u32(dyn + STAGES * BM * APITCH);
    int grp01 = (lane >> 3) & 1;   // matrix-pair selector within x4
    int grp23 = lane >> 4;
    // A: m0..m3 = (rows 0-7,k0-3),(rows 8-15,k0-3),(rows 0-7,k4-7),(rows 8-15,k4-7)
    uint32_t aoff = (uint32_t)(((wm * 64 + (lane & 7) + 8 * grp01) * APITCH
                                + 4 * grp23) * 4);
    // B: m0..m3 = (tn even,f0),(tn even,f1),(tn odd,f0),(tn odd,f1)
    uint32_t boff = (uint32_t)(((wn * 64 + grp23 * 8 + (lane & 7)) * APITCH
                                + 4 * grp01) * 4);

    issue(0, 0);
    issue(1, BK);
    issue(2, 2 * BK);

    for (int tt = 0; tt < nt; ++tt) {
        int buf = tt % STAGES;
        CP_WAIT2();
        __syncthreads();

        int nk = tt + 3;
        if (nk < nt) issue(nk % STAGES, nk * BK);
        else CP_COMMIT();   // empty group keeps wait_group arithmetic exact

        uint32_t as_s = as_base + (uint32_t)(buf * BM * APITCH * 4) + aoff;
        uint32_t ws_s = ws_base + (uint32_t)(buf * BN * APITCH * 4) + boff;

#pragma unroll
        for (int kk = 0; kk < BK; kk += 8) {
            uint32_t af[4][4], bf4[4][4];
#pragma unroll
            for (int tm = 0; tm < 4; ++tm)
                ldsm4(af[tm], as_s + kk * 4 + tm * (16 * APITCH * 4));
#pragma unroll
            for (int tnp = 0; tnp < 4; ++tnp)
                ldsm4(bf4[tnp], ws_s + kk * 4 + tnp * (16 * APITCH * 4));
#pragma unroll
            for (int tm = 0; tm < 4; ++tm)
#pragma unroll
                for (int tn = 0; tn < 8; ++tn)
                    mma_tf32(acc[tm][tn], af[tm], &bf4[tn >> 1][(tn & 1) << 1]);
        }
    }

    // epilogue: c0:(r, 2t) c1:(r, 2t+1) c2:(r+8, 2t) c3:(r+8, 2t+1)
    int rbase = m0 + wm * 64 + g;
    int cbase = n0 + wn * 64 + 2 * t;
#pragma unroll
    for (int tm = 0; tm < 4; ++tm) {
#pragma unroll
        for (int tn = 0; tn < 8; ++tn) {
#pragma unroll
            for (int r = 0; r < 4; ++r) {
                int m = rbase + tm * 16 + ((r >> 1) ? 8 : 0);
                int col = cbase + tn * 8 + (r & 1);
                int b = m >> 10, n = m & 1023;
                if (mode == 0) {
                    g_h[(size_t)m * Ncol + col] = acc[tm][tn][r] + bias[col];
                } else if (mode == 2) {
                    g_msg[(size_t)m * 1024 + col] = acc[tm][tn][r] + bias[col];
                } else if (mode == 3) {
                    Cout[(size_t)m * Ncol + col] =
                        acc[tm][tn][r] + bias[col] + resid[(size_t)m * Ncol + col];
                } else { // mode 1: packed QKV (columns are permuted logical cols)
                    float v = acc[tm][tn][r] + bias[qkv_perm(col)];
                    int s = col >> 10;
                    int w = col & 1023;
                    int h = w >> 6;
                    int d = w & 63;
                    size_t di = (((size_t)(b * HH + h)) * NN + n) * HDIM + d;
                    if (s == 0) g_q[di] = v;
                    else if (s == 1) g_k[di] = v;
                    else g_v[di] = v;
                }
            }
        }
    }
}

// ---------------------------------------------------------------------------
// RoPE in-place on g_q and g_k.  encoding: [2, B, 1, N, HD]
// ---------------------------------------------------------------------------
__global__ void rope_kernel(const float* __restrict__ enc)
{
    const int PH = BB * HH * NN * HDIM / 2;
    int p = blockIdx.x * blockDim.x + threadIdx.x;
    if (p >= 2 * PH) return;
    float* t = (p < PH) ? g_q : g_k;
    int pp = (p < PH) ? p : p - PH;
    int e = pp * 2;
    int d = e & 63;
    int n = (e >> 6) & 1023;
    int bh = e >> 16;
    int b = bh >> 4;
    float t0 = t[e], t1 = t[e + 1];
    size_t eb = ((size_t)(b * NN + n)) * HDIM + d;
    const int SINOFF = BB * NN * HDIM;
    float c0 = enc[eb], c1 = enc[eb + 1];
    float s0 = enc[eb + SINOFF], s1 = enc[eb + SINOFF + 1];
    t[e]     = t0 * c0 - t1 * s0;
    t[e + 1] = t1 * c1 + t0 * s1;
}

// ---------------------------------------------------------------------------
// Flash attention on tensor cores (tf32 m16n8k8, raw fp32 operands).
// 128 query rows (8 warps x 16), key tiles of 64, fixed-max softmax.
// 3-stage cp.async ring for K/V; K fragments via ldmatrix.x4.
// ---------------------------------------------------------------------------
#define KP 68
#define VP 72
#define ATT_STAGES 3
#define ATT_SMEM (ATT_STAGES * 64 * (KP + VP) * 4)

__global__ __launch_bounds__(256, 2) void attn_kernel()
{
    extern __shared__ float adyn[];
    float (*Ks)[64][KP] = (float(*)[64][KP])adyn;
    float (*Vs)[64][VP] = (float(*)[64][VP])(adyn + ATT_STAGES * 64 * KP);

    int bh = blockIdx.y;
    int qt = blockIdx.x;
    int tid = threadIdx.x;
    int lane = tid & 31;
    int wid = tid >> 5;
    int g = lane >> 2, t = lane & 3;

    const float* qbase = g_q + (size_t)bh * NN * HDIM + (size_t)qt * 128 * HDIM;
    const float* kbase = g_k + (size_t)bh * NN * HDIM;
    const float* vbase = g_v + (size_t)bh * NN * HDIM;

    auto issueKV = [&](int s, int kt2) {
        const float* kb = kbase + (size_t)kt2 * 64 * HDIM;
        const float* vb = vbase + (size_t)kt2 * 64 * HDIM;
#pragma unroll
        for (int h2 = 0; h2 < 4; ++h2) {
            int f = tid + h2 * 256;
            int r = f >> 4, cq = (f & 15) * 4;
            CP_ASYNC16(smem_u32(&Ks[s][r][cq]), kb + (size_t)r * HDIM + cq);
            CP_ASYNC16(smem_u32(&Vs[s][r][cq]), vb + (size_t)r * HDIM + cq);
        }
        CP_COMMIT();
    };

    uint32_t qf[8][4];
    {
        const float* q0 = qbase + (size_t)(wid * 16 + g) * HDIM;
        const float* q1 = q0 + 8 * HDIM;
#pragma unroll
        for (int kc = 0; kc < 8; ++kc) {
            int k0 = kc * 8 + t;
            qf[kc][0] = __float_as_uint(q0[k0] * 0.125f);
            qf[kc][1] = __float_as_uint(q1[k0] * 0.125f);
            qf[kc][2] = __float_as_uint(q0[k0 + 4] * 0.125f);
            qf[kc][3] = __float_as_uint(q1[k0 + 4] * 0.125f);
        }
    }

    float l0 = 0.f, l1 = 0.f;
    float O[8][4];
#pragma unroll
    for (int i = 0; i < 8; ++i)
#pragma unroll
        for (int r = 0; r < 4; ++r) O[i][r] = 0.f;

    const int sl0 = (lane & ~3) | (t >> 1);
    const int sl1 = sl0 + 2;

    uint32_t ks_base = smem_u32(adyn);
    int grp01 = (lane >> 3) & 1;
    int grp23 = lane >> 4;
    uint32_t koff = (uint32_t)(((grp23 * 8 + (lane & 7)) * KP + 4 * grp01) * 4);

    issueKV(0, 0);
    issueKV(1, 1);

    for (int kt = 0; kt < 16; ++kt) {
        int buf = kt % ATT_STAGES;
        CP_WAIT1();
        __syncthreads();

        int nk = kt + 2;
        if (nk < 16) issueKV(nk % ATT_STAGES, nk);
        else CP_COMMIT();

        float S[8][4];
#pragma unroll
        for (int i = 0; i < 8; ++i)
#pragma unroll
            for (int r = 0; r < 4; ++r) S[i][r] = 0.f;

        uint32_t ks_s = ks_base + (uint32_t)(buf * 64 * KP * 4) + koff;
#pragma unroll
        for (int kc = 0; kc < 8; ++kc) {
#pragma unroll
            for (int knp = 0; knp < 4; ++knp) {
                uint32_t kf[4];
                ldsm4(kf, ks_s + kc * 32 + knp * (16 * KP * 4));
                mma_tf32(S[2 * knp],     qf[kc], &kf[0]);
                mma_tf32(S[2 * knp + 1], qf[kc], &kf[2]);
            }
        }

#pragma unroll
        for (int i = 0; i < 8; ++i) {
            float p0 = __expf(S[i][0]);
            float p1 = __expf(S[i][1]);
            float p2 = __expf(S[i][2]);
            float p3 = __expf(S[i][3]);
            l0 += p0 + p1; l1 += p2 + p3;
            S[i][0] = p0; S[i][1] = p1; S[i][2] = p2; S[i][3] = p3;
        }

#pragma unroll
        for (int kc = 0; kc < 8; ++kc) {
            float v00 = __shfl_sync(0xffffffffu, S[kc][0], sl0);
            float v01 = __shfl_sync(0xffffffffu, S[kc][1], sl0);
            float v10 = __shfl_sync(0xffffffffu, S[kc][2], sl0);
            float v11 = __shfl_sync(0xffffffffu, S[kc][3], sl0);
            float v20 = __shfl_sync(0xffffffffu, S[kc][0], sl1);
            float v21 = __shfl_sync(0xffffffffu, S[kc][1], sl1);
            float v30 = __shfl_sync(0xffffffffu, S[kc][2], sl1);
            float v31 = __shfl_sync(0xffffffffu, S[kc][3], sl1);
            uint32_t af[4];
            af[0] = __float_as_uint((t & 1) ? v01 : v00);
            af[1] = __float_as_uint((t & 1) ? v11 : v10);
            af[2] = __float_as_uint((t & 1) ? v21 : v20);
            af[3] = __float_as_uint((t & 1) ? v31 : v30);
#pragma unroll
            for (int ntile = 0; ntile < 8; ++ntile) {
                uint32_t bf[2];
                bf[0] = __float_as_uint(Vs[buf][kc * 8 + t][ntile * 8 + g]);
                bf[1] = __float_as_uint(Vs[buf][kc * 8 + t + 4][ntile * 8 + g]);
                mma_tf32(O[ntile], af, bf);
            }
        }
    }

    l0 += __shfl_xor_sync(0xffffffffu, l0, 1);
    l0 += __shfl_xor_sync(0xffffffffu, l0, 2);
    l1 += __shfl_xor_sync(0xffffffffu, l1, 1);
    l1 += __shfl_xor_sync(0xffffffffu, l1, 2);

    float i0 = 1.f / l0, i1 = 1.f / l1;
    int b = bh >> 4, h = bh & 15;
    int r0 = qt * 128 + wid * 16 + g;
    float* d0 = g_ctx + (((size_t)(b * NN + r0)) * HH + h) * HDIM;
    float* d1 = g_ctx + (((size_t)(b * NN + r0 + 8)) * HH + h) * HDIM;
#pragma unroll
    for (int ntile = 0; ntile < 8; ++ntile) {
        int c = ntile * 8 + 2 * t;
        d0[c]     = O[ntile][0] * i0;
        d0[c + 1] = O[ntile][1] * i0;
        d1[c]     = O[ntile][2] * i1;
        d1[c + 1] = O[ntile][3] * i1;
    }
}

// ---------------------------------------------------------------------------
// LayerNorm(2048) + exact GELU, in-place on g_h.
// ---------------------------------------------------------------------------
__global__ __launch_bounds__(256) void ln_gelu_kernel(
    const float* __restrict__ lng, const float* __restrict__ lnb)
{
    int row = blockIdx.x;
    float* hr = g_h + (size_t)row * 2048;
    int tid = threadIdx.x;
    float v[8];
    float s = 0.f, s2 = 0.f;
#pragma unroll
    for (int i = 0; i < 8; ++i) {
        float t = hr[tid + i * 256];
        v[i] = t; s += t; s2 += t * t;
    }
#pragma unroll
    for (int o = 16; o; o >>= 1) {
        s  += __shfl_xor_sync(0xffffffffu, s,  o);
        s2 += __shfl_xor_sync(0xffffffffu, s2, o);
    }
    __shared__ float rs[8], rs2[8];
    __shared__ float sm, si;
    int wid = tid >> 5, lane = tid & 31;
    if (!lane) { rs[wid] = s; rs2[wid] = s2; }
    __syncthreads();
    if (tid == 0) {
        float S = 0.f, S2 = 0.f;
#pragma unroll
        for (int i = 0; i < 8; ++i) { S += rs[i]; S2 += rs2[i]; }
        float mean = S * (1.f / 2048.f);
        float var = S2 * (1.f / 2048.f) - mean * mean;
        sm = mean;
        si = rsqrtf(var + 1e-5f);
    }
    __syncthreads();
    float mean = sm, inv = si;
#pragma unroll
    for (int i = 0; i < 8; ++i) {
        int col = tid + i * 256;
        float t = (v[i] - mean) * inv * lng[col] + lnb[col];
        t = 0.5f * t * (1.f + erff(t * 0.70710678118654752f));
        hr[col] = t;
    }
}

// ---------------------------------------------------------------------------
extern "C" void kernel_launch(void* const* d_in, const int* in_sizes, int n_in,
                              void* d_out, int out_size)
{
    const float* x       = (const float*)d_in[0];
    const float* enc     = (const float*)d_in[1];
    const float* Wqkv_w  = (const float*)d_in[2];
    const float* Wqkv_b  = (const float*)d_in[3];
    const float* out_w   = (const float*)d_in[4];
    const float* out_b   = (const float*)d_in[5];
    const float* ffn1_w  = (const float*)d_in[6];
    const float* ffn1_b  = (const float*)d_in[7];
    const float* ln_g    = (const float*)d_in[8];
    const float* ln_b    = (const float*)d_in[9];
    const float* ffn2_w  = (const float*)d_in[10];
    const float* ffn2_b  = (const float*)d_in[11];
    float* out = (float*)d_out;

    cudaFuncSetAttribute(gemm_kernel,
                         cudaFuncAttributeMaxDynamicSharedMemorySize, GEMM_SMEM);
    cudaFuncSetAttribute(attn_kernel,
                         cudaFuncAttributeMaxDynamicSharedMemorySize, ATT_SMEM);

    // 1) QKV projection (permuted W) -> packed q/k/v  (M=4096, N=3072, K=1024)
    gemm_kernel<<<dim3(3072 / BN, MROWS / BM), 128, GEMM_SMEM>>>(
        x, Wqkv_w, Wqkv_b, nullptr, nullptr, MROWS, 3072, 1024, 1);

    // 2) RoPE on q and k
    rope_kernel<<<(2 * BB * HH * NN * HDIM / 2 + 255) / 256, 256>>>(enc);

    // 3) attention -> g_ctx [B,N,H,HD]
    attn_kernel<<<dim3(NN / 128, BB * HH), 256, ATT_SMEM>>>();

    // 4) out projection -> g_msg   (M=4096, N=1024, K=1024)
    gemm_kernel<<<dim3(1024 / BN, MROWS / BM), 128, GEMM_SMEM>>>(
        nullptr, out_w, out_b, nullptr, nullptr, MROWS, 1024, 1024, 2);

    // 5) FFN1 (A = virtual concat of x and g_msg) -> g_h  (M=4096, N=2048, K=2048)
    gemm_kernel<<<dim3(2048 / BN, MROWS / BM), 128, GEMM_SMEM>>>(
        x, ffn1_w, ffn1_b, nullptr, nullptr, MROWS, 2048, 2048, 0);

    // 6) LayerNorm + GELU in-place
    ln_gelu_kernel<<<MROWS, 256>>>(ln_g, ln_b);

    // 7) FFN2 + residual -> d_out   (M=4096, N=1024, K=2048)
    gemm_kernel<<<dim3(1024 / BN, MROWS / BM), 128, GEMM_SMEM>>>(
        x, ffn2_w, ffn2_b, out, x, MROWS, 1024, 2048, 3);
}

// round 15
// speedup vs baseline: 1.1589x; 1.0308x over previous
#include <cuda_runtime.h>
#include <math.h>
#include <stdint.h>

// Problem constants
#define BB 4
#define NN 1024
#define DD 1024
#define HH 16
#define HDIM 64
#define MROWS (BB * NN)          // 4096
#define SINOFF (BB * NN * HDIM)  // offset of sin plane in encoding

// Scratch (device globals; no allocations allowed)
__device__ float g_q[BB * HH * NN * HDIM];   // [B,H,N,HD]
__device__ float g_k[BB * HH * NN * HDIM];
__device__ float g_v[BB * HH * NN * HDIM];
__device__ float g_ctx[BB * NN * DD];        // [B,N,H,HD]
__device__ float g_msg[MROWS * DD];          // out-proj result (message)
__device__ float g_h[MROWS * 2 * DD];        // FFN hidden, rows of 2048

__device__ __forceinline__ void mma_tf32(float* c, const uint32_t* a, const uint32_t* b) {
    asm volatile(
        "mma.sync.aligned.m16n8k8.row.col.f32.tf32.tf32.f32 "
        "{%0,%1,%2,%3}, {%4,%5,%6,%7}, {%8,%9}, {%0,%1,%2,%3};"
        : "+f"(c[0]), "+f"(c[1]), "+f"(c[2]), "+f"(c[3])
        : "r"(a[0]), "r"(a[1]), "r"(a[2]), "r"(a[3]), "r"(b[0]), "r"(b[1]));
}

// ldmatrix x4: four 8-row x 16-byte tiles; as tf32, lane l gets (row l/4, col l%4)
__device__ __forceinline__ void ldsm4(uint32_t* r, uint32_t addr) {
    asm volatile(
        "ldmatrix.sync.aligned.m8n8.x4.shared.b16 {%0,%1,%2,%3}, [%4];"
        : "=r"(r[0]), "=r"(r[1]), "=r"(r[2]), "=r"(r[3]) : "r"(addr));
}

__device__ __forceinline__ uint32_t smem_u32(const void* p) {
    return (uint32_t)__cvta_generic_to_shared(p);
}
#define CP_ASYNC16(dst, src) \
    asm volatile("cp.async.cg.shared.global [%0], [%1], 16;" :: "r"(dst), "l"(src))
#define CP_COMMIT() asm volatile("cp.async.commit_group;" ::: "memory")
#define CP_WAIT2()  asm volatile("cp.async.wait_group 2;" ::: "memory")
#define CP_WAIT1()  asm volatile("cp.async.wait_group 1;" ::: "memory")

// QKV column permutation: logical col' in [0,3072) = [q | k | v], d contiguous.
// orig W row = h*192 + d*3 + s  where s = col'>>10, h = (col'&1023)>>6, d = col'&63
__device__ __forceinline__ int qkv_perm(int colp) {
    int s = colp >> 10;
    int w = colp & 1023;
    int h = w >> 6;
    int d = w & 63;
    return h * 192 + d * 3 + s;
}

// ---------------------------------------------------------------------------
// TF32 tensor-core GEMM:  C[M,Ncol] = A[M,K] @ W[Ncol,K]^T + bias
// 128x128 block tile, 4 warps of 64x64, 128 threads, 4-stage cp.async,
// ONE barrier per K-tile; fragments via ldmatrix.x4. 2 CTAs/SM.
// mode 0: A=concat(x, g_msg) -> g_h            (FFN1, virtual concat)
// mode 1: A=Ain(x), W rows permuted -> packed q/k/v with FUSED RoPE
//         (resid parameter carries the encoding pointer)
// mode 2: A=g_ctx  -> g_msg                    (out-proj)
// mode 3: A=g_h    -> Cout = resid + result    (FFN2 + residual)
// ---------------------------------------------------------------------------
#define BM 128
#define BN 128
#define BK 16
#define APITCH 20   // 80B rows: 16B-aligned chunks; LDSM wavefronts conflict-free
#define STAGES 4
#define GEMM_SMEM (STAGES * (BM + BN) * APITCH * 4)   // 81920 B

__global__ __launch_bounds__(128) void gemm_kernel(
    const float* __restrict__ Ain, const float* __restrict__ W,
    const float* __restrict__ bias, float* __restrict__ Cout,
    const float* __restrict__ resid, int M, int Ncol, int K, int mode)
{
    extern __shared__ float dyn[];
    float (*As)[BM][APITCH] = (float(*)[BM][APITCH])dyn;
    float (*Ws)[BN][APITCH] = (float(*)[BN][APITCH])(dyn + STAGES * BM * APITCH);

    const float* A = (mode == 2) ? g_ctx : (mode == 3) ? g_h : Ain;

    int tid = threadIdx.x;
    int lane = tid & 31;
    int wid = tid >> 5;
    int g = lane >> 2, t = lane & 3;
    int wm = wid >> 1;
    int wn = wid & 1;
    int m0 = blockIdx.y * BM, n0 = blockIdx.x * BN;

    float acc[4][8][4];
#pragma unroll
    for (int i = 0; i < 4; ++i)
#pragma unroll
        for (int j = 0; j < 8; ++j)
#pragma unroll
            for (int r = 0; r < 4; ++r) acc[i][j][r] = 0.f;

    int nt = K / BK;
    int lrow = tid >> 2, lkq = (tid & 3) * 4;   // this thread's load slot

    // Pre-resolved W row indices (permuted for QKV), 4 rows per thread
    int wrow[4];
#pragma unroll
    for (int h = 0; h < 4; ++h) {
        int row = n0 + lrow + h * 32;
        wrow[h] = (mode == 1) ? qkv_perm(row) : row;
    }

    auto issue = [&](int s, int k0) {
        const float* abase;
        if (mode == 0)   // virtual concat([x, g_msg]) along K
            abase = (k0 < 1024) ? (Ain + k0) : (g_msg + (k0 - 1024));
        else
            abase = A + k0;
        int ak = (mode == 0) ? 1024 : K;
#pragma unroll
        for (int h = 0; h < 4; ++h) {
            int row = lrow + h * 32;
            CP_ASYNC16(smem_u32(&As[s][row][lkq]),
                       abase + (size_t)(m0 + row) * ak + lkq);
            CP_ASYNC16(smem_u32(&Ws[s][row][lkq]),
                       W + (size_t)wrow[h] * K + k0 + lkq);
        }
        CP_COMMIT();
    };

    // ldmatrix lane-address offsets (bytes, within one stage)
    uint32_t as_base = smem_u32(dyn);
    uint32_t ws_base = smem_u32(dyn + STAGES * BM * APITCH);
    int grp01 = (lane >> 3) & 1;   // matrix-pair selector within x4
    int grp23 = lane >> 4;
    // A: m0..m3 = (rows 0-7,k0-3),(rows 8-15,k0-3),(rows 0-7,k4-7),(rows 8-15,k4-7)
    uint32_t aoff = (uint32_t)(((wm * 64 + (lane & 7) + 8 * grp01) * APITCH
                                + 4 * grp23) * 4);
    // B: m0..m3 = (tn even,f0),(tn even,f1),(tn odd,f0),(tn odd,f1)
    uint32_t boff = (uint32_t)(((wn * 64 + grp23 * 8 + (lane & 7)) * APITCH
                                + 4 * grp01) * 4);

    issue(0, 0);
    issue(1, BK);
    issue(2, 2 * BK);

    for (int tt = 0; tt < nt; ++tt) {
        int buf = tt % STAGES;
        CP_WAIT2();
        __syncthreads();

        int nk = tt + 3;
        if (nk < nt) issue(nk % STAGES, nk * BK);
        else CP_COMMIT();   // empty group keeps wait_group arithmetic exact

        uint32_t as_s = as_base + (uint32_t)(buf * BM * APITCH * 4) + aoff;
        uint32_t ws_s = ws_base + (uint32_t)(buf * BN * APITCH * 4) + boff;

#pragma unroll
        for (int kk = 0; kk < BK; kk += 8) {
            uint32_t af[4][4], bf4[4][4];
#pragma unroll
            for (int tm = 0; tm < 4; ++tm)
                ldsm4(af[tm], as_s + kk * 4 + tm * (16 * APITCH * 4));
#pragma unroll
            for (int tnp = 0; tnp < 4; ++tnp)
                ldsm4(bf4[tnp], ws_s + kk * 4 + tnp * (16 * APITCH * 4));
#pragma unroll
            for (int tm = 0; tm < 4; ++tm)
#pragma unroll
                for (int tn = 0; tn < 8; ++tn)
                    mma_tf32(acc[tm][tn], af[tm], &bf4[tn >> 1][(tn & 1) << 1]);
        }
    }

    // epilogue: c0:(r, 2t) c1:(r, 2t+1) c2:(r+8, 2t) c3:(r+8, 2t+1)
    int rbase = m0 + wm * 64 + g;
    int cbase = n0 + wn * 64 + 2 * t;

    if (mode == 1) {
        // packed QKV with fused RoPE; resid carries the encoding pointer
        const float* enc = resid;
        int col0 = cbase;                 // even; per tn add tn*8 (stays even)
#pragma unroll
        for (int tn = 0; tn < 8; ++tn) {
            int c0 = col0 + tn * 8;
            int s = c0 >> 10;
            int w = c0 & 1023;
            int h = w >> 6;
            int d = w & 63;               // even
            float b0 = bias[qkv_perm(c0)];
            float b1 = bias[qkv_perm(c0 + 1)];
#pragma unroll
            for (int tm = 0; tm < 4; ++tm) {
#pragma unroll
                for (int half = 0; half < 2; ++half) {
                    int m = rbase + tm * 16 + half * 8;
                    int b = m >> 10, n = m & 1023;
                    float v0 = acc[tm][tn][half * 2]     + b0;
                    float v1 = acc[tm][tn][half * 2 + 1] + b1;
                    if (s < 2) {   // RoPE on q and k only
                        size_t eb = ((size_t)(b * NN + n)) * HDIM + d;
                        float c_0 = enc[eb], c_1 = enc[eb + 1];
                        float s_0 = enc[eb + SINOFF], s_1 = enc[eb + SINOFF + 1];
                        float nv0 = v0 * c_0 - v1 * s_0;
                        float nv1 = v1 * c_1 + v0 * s_1;
                        v0 = nv0; v1 = nv1;
                    }
                    size_t di = (((size_t)(b * HH + h)) * NN + n) * HDIM + d;
                    float* dst = (s == 0) ? g_q : (s == 1) ? g_k : g_v;
                    *(float2*)(dst + di) = make_float2(v0, v1);
                }
            }
        }
    } else {
#pragma unroll
        for (int tm = 0; tm < 4; ++tm) {
#pragma unroll
            for (int tn = 0; tn < 8; ++tn) {
#pragma unroll
                for (int r = 0; r < 4; ++r) {
                    int m = rbase + tm * 16 + ((r >> 1) ? 8 : 0);
                    int col = cbase + tn * 8 + (r & 1);
                    float v = acc[tm][tn][r] + bias[col];
                    if (mode == 0) {
                        g_h[(size_t)m * Ncol + col] = v;
                    } else if (mode == 2) {
                        g_msg[(size_t)m * 1024 + col] = v;
                    } else {
                        Cout[(size_t)m * Ncol + col] =
                            v + resid[(size_t)m * Ncol + col];
                    }
                }
            }
        }
    }
}

// ---------------------------------------------------------------------------
// Flash attention on tensor cores (tf32 m16n8k8, raw fp32 operands).
// 128 query rows (8 warps x 16), key tiles of 64, fixed-max softmax.
// 3-stage cp.async ring for K/V; K fragments via ldmatrix.x4.
// ---------------------------------------------------------------------------
#define KP 68
#define VP 72
#define ATT_STAGES 3
#define ATT_SMEM (ATT_STAGES * 64 * (KP + VP) * 4)

__global__ __launch_bounds__(256, 2) void attn_kernel()
{
    extern __shared__ float adyn[];
    float (*Ks)[64][KP] = (float(*)[64][KP])adyn;
    float (*Vs)[64][VP] = (float(*)[64][VP])(adyn + ATT_STAGES * 64 * KP);

    int bh = blockIdx.y;
    int qt = blockIdx.x;
    int tid = threadIdx.x;
    int lane = tid & 31;
    int wid = tid >> 5;
    int g = lane >> 2, t = lane & 3;

    const float* qbase = g_q + (size_t)bh * NN * HDIM + (size_t)qt * 128 * HDIM;
    const float* kbase = g_k + (size_t)bh * NN * HDIM;
    const float* vbase = g_v + (size_t)bh * NN * HDIM;

    auto issueKV = [&](int s, int kt2) {
        const float* kb = kbase + (size_t)kt2 * 64 * HDIM;
        const float* vb = vbase + (size_t)kt2 * 64 * HDIM;
#pragma unroll
        for (int h2 = 0; h2 < 4; ++h2) {
            int f = tid + h2 * 256;
            int r = f >> 4, cq = (f & 15) * 4;
            CP_ASYNC16(smem_u32(&Ks[s][r][cq]), kb + (size_t)r * HDIM + cq);
            CP_ASYNC16(smem_u32(&Vs[s][r][cq]), vb + (size_t)r * HDIM + cq);
        }
        CP_COMMIT();
    };

    uint32_t qf[8][4];
    {
        const float* q0 = qbase + (size_t)(wid * 16 + g) * HDIM;
        const float* q1 = q0 + 8 * HDIM;
#pragma unroll
        for (int kc = 0; kc < 8; ++kc) {
            int k0 = kc * 8 + t;
            qf[kc][0] = __float_as_uint(q0[k0] * 0.125f);
            qf[kc][1] = __float_as_uint(q1[k0] * 0.125f);
            qf[kc][2] = __float_as_uint(q0[k0 + 4] * 0.125f);
            qf[kc][3] = __float_as_uint(q1[k0 + 4] * 0.125f);
        }
    }

    float l0 = 0.f, l1 = 0.f;
    float O[8][4];
#pragma unroll
    for (int i = 0; i < 8; ++i)
#pragma unroll
        for (int r = 0; r < 4; ++r) O[i][r] = 0.f;

    const int sl0 = (lane & ~3) | (t >> 1);
    const int sl1 = sl0 + 2;

    uint32_t ks_base = smem_u32(adyn);
    int grp01 = (lane >> 3) & 1;
    int grp23 = lane >> 4;
    uint32_t koff = (uint32_t)(((grp23 * 8 + (lane & 7)) * KP + 4 * grp01) * 4);

    issueKV(0, 0);
    issueKV(1, 1);

    for (int kt = 0; kt < 16; ++kt) {
        int buf = kt % ATT_STAGES;
        CP_WAIT1();
        __syncthreads();

        int nk = kt + 2;
        if (nk < 16) issueKV(nk % ATT_STAGES, nk);
        else CP_COMMIT();

        float S[8][4];
#pragma unroll
        for (int i = 0; i < 8; ++i)
#pragma unroll
            for (int r = 0; r < 4; ++r) S[i][r] = 0.f;

        uint32_t ks_s = ks_base + (uint32_t)(buf * 64 * KP * 4) + koff;
#pragma unroll
        for (int kc = 0; kc < 8; ++kc) {
#pragma unroll
            for (int knp = 0; knp < 4; ++knp) {
                uint32_t kf[4];
                ldsm4(kf, ks_s + kc * 32 + knp * (16 * KP * 4));
                mma_tf32(S[2 * knp],     qf[kc], &kf[0]);
                mma_tf32(S[2 * knp + 1], qf[kc], &kf[2]);
            }
        }

#pragma unroll
        for (int i = 0; i < 8; ++i) {
            float p0 = __expf(S[i][0]);
            float p1 = __expf(S[i][1]);
            float p2 = __expf(S[i][2]);
            float p3 = __expf(S[i][3]);
            l0 += p0 + p1; l1 += p2 + p3;
            S[i][0] = p0; S[i][1] = p1; S[i][2] = p2; S[i][3] = p3;
        }

#pragma unroll
        for (int kc = 0; kc < 8; ++kc) {
            float v00 = __shfl_sync(0xffffffffu, S[kc][0], sl0);
            float v01 = __shfl_sync(0xffffffffu, S[kc][1], sl0);
            float v10 = __shfl_sync(0xffffffffu, S[kc][2], sl0);
            float v11 = __shfl_sync(0xffffffffu, S[kc][3], sl0);
            float v20 = __shfl_sync(0xffffffffu, S[kc][0], sl1);
            float v21 = __shfl_sync(0xffffffffu, S[kc][1], sl1);
            float v30 = __shfl_sync(0xffffffffu, S[kc][2], sl1);
            float v31 = __shfl_sync(0xffffffffu, S[kc][3], sl1);
            uint32_t af[4];
            af[0] = __float_as_uint((t & 1) ? v01 : v00);
            af[1] = __float_as_uint((t & 1) ? v11 : v10);
            af[2] = __float_as_uint((t & 1) ? v21 : v20);
            af[3] = __float_as_uint((t & 1) ? v31 : v30);
#pragma unroll
            for (int ntile = 0; ntile < 8; ++ntile) {
                uint32_t bf[2];
                bf[0] = __float_as_uint(Vs[buf][kc * 8 + t][ntile * 8 + g]);
                bf[1] = __float_as_uint(Vs[buf][kc * 8 + t + 4][ntile * 8 + g]);
                mma_tf32(O[ntile], af, bf);
            }
        }
    }

    l0 += __shfl_xor_sync(0xffffffffu, l0, 1);
    l0 += __shfl_xor_sync(0xffffffffu, l0, 2);
    l1 += __shfl_xor_sync(0xffffffffu, l1, 1);
    l1 += __shfl_xor_sync(0xffffffffu, l1, 2);

    float i0 = 1.f / l0, i1 = 1.f / l1;
    int b = bh >> 4, h = bh & 15;
    int r0 = qt * 128 + wid * 16 + g;
    float* d0 = g_ctx + (((size_t)(b * NN + r0)) * HH + h) * HDIM;
    float* d1 = g_ctx + (((size_t)(b * NN + r0 + 8)) * HH + h) * HDIM;
#pragma unroll
    for (int ntile = 0; ntile < 8; ++ntile) {
        int c = ntile * 8 + 2 * t;
        d0[c]     = O[ntile][0] * i0;
        d0[c + 1] = O[ntile][1] * i0;
        d1[c]     = O[ntile][2] * i1;
        d1[c + 1] = O[ntile][3] * i1;
    }
}

// ---------------------------------------------------------------------------
// LayerNorm(2048) + exact GELU, in-place on g_h.
// ---------------------------------------------------------------------------
__global__ __launch_bounds__(256) void ln_gelu_kernel(
    const float* __restrict__ lng, const float* __restrict__ lnb)
{
    int row = blockIdx.x;
    float* hr = g_h + (size_t)row * 2048;
    int tid = threadIdx.x;
    float v[8];
    float s = 0.f, s2 = 0.f;
#pragma unroll
    for (int i = 0; i < 8; ++i) {
        float t = hr[tid + i * 256];
        v[i] = t; s += t; s2 += t * t;
    }
#pragma unroll
    for (int o = 16; o; o >>= 1) {
        s  += __shfl_xor_sync(0xffffffffu, s,  o);
        s2 += __shfl_xor_sync(0xffffffffu, s2, o);
    }
    __shared__ float rs[8], rs2[8];
    __shared__ float sm, si;
    int wid = tid >> 5, lane = tid & 31;
    if (!lane) { rs[wid] = s; rs2[wid] = s2; }
    __syncthreads();
    if (tid == 0) {
        float S = 0.f, S2 = 0.f;
#pragma unroll
        for (int i = 0; i < 8; ++i) { S += rs[i]; S2 += rs2[i]; }
        float mean = S * (1.f / 2048.f);
        float var = S2 * (1.f / 2048.f) - mean * mean;
        sm = mean;
        si = rsqrtf(var + 1e-5f);
    }
    __syncthreads();
    float mean = sm, inv = si;
#pragma unroll
    for (int i = 0; i < 8; ++i) {
        int col = tid + i * 256;
        float t = (v[i] - mean) * inv * lng[col] + lnb[col];
        t = 0.5f * t * (1.f + erff(t * 0.70710678118654752f));
        hr[col] = t;
    }
}

// ---------------------------------------------------------------------------
extern "C" void kernel_launch(void* const* d_in, const int* in_sizes, int n_in,
                              void* d_out, int out_size)
{
    const float* x       = (const float*)d_in[0];
    const float* enc     = (const float*)d_in[1];
    const float* Wqkv_w  = (const float*)d_in[2];
    const float* Wqkv_b  = (const float*)d_in[3];
    const float* out_w   = (const float*)d_in[4];
    const float* out_b   = (const float*)d_in[5];
    const float* ffn1_w  = (const float*)d_in[6];
    const float* ffn1_b  = (const float*)d_in[7];
    const float* ln_g    = (const float*)d_in[8];
    const float* ln_b    = (const float*)d_in[9];
    const float* ffn2_w  = (const float*)d_in[10];
    const float* ffn2_b  = (const float*)d_in[11];
    float* out = (float*)d_out;

    cudaFuncSetAttribute(gemm_kernel,
                         cudaFuncAttributeMaxDynamicSharedMemorySize, GEMM_SMEM);
    cudaFuncSetAttribute(attn_kernel,
                         cudaFuncAttributeMaxDynamicSharedMemorySize, ATT_SMEM);

    // 1) QKV projection (permuted W) + fused RoPE -> packed q/k/v
    //    (enc passed via the resid parameter)
    gemm_kernel<<<dim3(3072 / BN, MROWS / BM), 128, GEMM_SMEM>>>(
        x, Wqkv_w, Wqkv_b, nullptr, enc, MROWS, 3072, 1024, 1);

    // 2) attention -> g_ctx [B,N,H,HD]
    attn_kernel<<<dim3(NN / 128, BB * HH), 256, ATT_SMEM>>>();

    // 3) out projection -> g_msg   (M=4096, N=1024, K=1024)
    gemm_kernel<<<dim3(1024 / BN, MROWS / BM), 128, GEMM_SMEM>>>(
        nullptr, out_w, out_b, nullptr, nullptr, MROWS, 1024, 1024, 2);

    // 4) FFN1 (A = virtual concat of x and g_msg) -> g_h  (M=4096, N=2048, K=2048)
    gemm_kernel<<<dim3(2048 / BN, MROWS / BM), 128, GEMM_SMEM>>>(
        x, ffn1_w, ffn1_b, nullptr, nullptr, MROWS, 2048, 2048, 0);

    // 5) LayerNorm + GELU in-place
    ln_gelu_kernel<<<MROWS, 256>>>(ln_g, ln_b);

    // 6) FFN2 + residual -> d_out   (M=4096, N=1024, K=2048)
    gemm_kernel<<<dim3(1024 / BN, MROWS / BM), 128, GEMM_SMEM>>>(
        x, ffn2_w, ffn2_b, out, x, MROWS, 1024, 2048, 3);
}